// round 1
// baseline (speedup 1.0000x reference)
#include <cuda_runtime.h>
#include <math.h>

// Problem shapes (fixed per reference setup_inputs)
// B=4, T=1024, D=4096, N=32 heads, KH=8 kv heads, H=128, G=4
// M_TOK = B*T = 4096 tokens
// qg: (4096, 32*256=8192)  [per head: 128 q | 128 gate]
// k,v: (4096, 8*128=1024)
// att(gated): (4096, 32*128=4096)

__device__ float g_qg [4096UL * 8192];
__device__ float g_k  [4096UL * 1024];
__device__ float g_v  [4096UL * 1024];
__device__ float g_att[4096UL * 4096];

// ---------------------------------------------------------------------------
// Tiled fp32 SGEMM: C[M,N] = A[M,K] @ B[K,N], all row-major, dims multiples of
// block tile (true for all 4 GEMMs here: M=4096, K=4096, N in {8192,1024,4096}).
// BM=BN=128, BK=16, 256 threads, 8x8 per-thread tile, float4 everywhere.
// ---------------------------------------------------------------------------
#define BM 128
#define BN 128
#define BK 16

__global__ __launch_bounds__(256) void sgemm_kernel(
    const float* __restrict__ A, const float* __restrict__ B,
    float* __restrict__ C, int M, int N, int K)
{
    __shared__ float As[BK][BM];   // transposed A tile
    __shared__ float Bs[BK][BN];

    const int tid = threadIdx.x;
    const int block_row = blockIdx.y * BM;
    const int block_col = blockIdx.x * BN;

    const int tr = (tid >> 4) * 8;   // 0..120
    const int tc = (tid & 15) * 8;   // 0..120

    float acc[8][8];
#pragma unroll
    for (int i = 0; i < 8; i++)
#pragma unroll
        for (int j = 0; j < 8; j++) acc[i][j] = 0.0f;

    for (int k0 = 0; k0 < K; k0 += BK) {
        // Load A tile (BM x BK) -> As transposed. 512 float4 slots, 2 per thread.
#pragma unroll
        for (int it = 0; it < 2; it++) {
            int s = tid + it * 256;
            int arow = s >> 2;               // 0..127
            int avc  = (s & 3) << 2;         // 0,4,8,12
            float4 av = *reinterpret_cast<const float4*>(
                &A[(size_t)(block_row + arow) * K + k0 + avc]);
            As[avc + 0][arow] = av.x;
            As[avc + 1][arow] = av.y;
            As[avc + 2][arow] = av.z;
            As[avc + 3][arow] = av.w;

            int brow = s >> 5;               // 0..15
            int bvc  = (s & 31) << 2;        // 0..124
            float4 bv = *reinterpret_cast<const float4*>(
                &B[(size_t)(k0 + brow) * N + block_col + bvc]);
            *reinterpret_cast<float4*>(&Bs[brow][bvc]) = bv;
        }
        __syncthreads();

#pragma unroll
        for (int k = 0; k < BK; k++) {
            float ar[8], br[8];
            float4 a0 = *reinterpret_cast<const float4*>(&As[k][tr]);
            float4 a1 = *reinterpret_cast<const float4*>(&As[k][tr + 4]);
            float4 b0 = *reinterpret_cast<const float4*>(&Bs[k][tc]);
            float4 b1 = *reinterpret_cast<const float4*>(&Bs[k][tc + 4]);
            ar[0]=a0.x; ar[1]=a0.y; ar[2]=a0.z; ar[3]=a0.w;
            ar[4]=a1.x; ar[5]=a1.y; ar[6]=a1.z; ar[7]=a1.w;
            br[0]=b0.x; br[1]=b0.y; br[2]=b0.z; br[3]=b0.w;
            br[4]=b1.x; br[5]=b1.y; br[6]=b1.z; br[7]=b1.w;
#pragma unroll
            for (int i = 0; i < 8; i++)
#pragma unroll
                for (int j = 0; j < 8; j++)
                    acc[i][j] = fmaf(ar[i], br[j], acc[i][j]);
        }
        __syncthreads();
    }

#pragma unroll
    for (int i = 0; i < 8; i++) {
        float4* cp = reinterpret_cast<float4*>(
            &C[(size_t)(block_row + tr + i) * N + block_col + tc]);
        cp[0] = make_float4(acc[i][0], acc[i][1], acc[i][2], acc[i][3]);
        cp[1] = make_float4(acc[i][4], acc[i][5], acc[i][6], acc[i][7]);
    }
}

// ---------------------------------------------------------------------------
// Fused RMSNorm + RoPE, in-place, one warp per (token, head) row of 128 floats.
// Rotary on dims [0,80): pair (h, h+40) == lane exchange at distance 10
// (4 dims/lane * 10 lanes = 40 dims).
// ---------------------------------------------------------------------------
__global__ void norm_rope_kernel(
    float* __restrict__ buf, const int* __restrict__ positions,
    const float* __restrict__ w, int nheads, int head_stride, int row_stride)
{
    const int gw   = (blockIdx.x * blockDim.x + threadIdx.x) >> 5;
    const int lane = threadIdx.x & 31;
    const int h_idx = gw % nheads;
    const int m     = gw / nheads;

    float* row = buf + (size_t)m * row_stride + (size_t)h_idx * head_stride;
    float4 x = *reinterpret_cast<const float4*>(row + 4 * lane);

    // RMS norm over H=128
    float ss = x.x*x.x + x.y*x.y + x.z*x.z + x.w*x.w;
#pragma unroll
    for (int o = 16; o; o >>= 1) ss += __shfl_xor_sync(0xffffffffu, ss, o);
    float r = rsqrtf(ss * (1.0f / 128.0f) + 1e-6f);
    float4 wv = *reinterpret_cast<const float4*>(w + 4 * lane);
    x.x *= r * (1.0f + wv.x);
    x.y *= r * (1.0f + wv.y);
    x.z *= r * (1.0f + wv.z);
    x.w *= r * (1.0f + wv.w);

    // RoPE (convergent shuffles for all lanes)
    const int h0 = lane * 4;
    const int partner = (lane < 10) ? lane + 10 : ((lane < 20) ? lane - 10 : lane);
    float px = __shfl_sync(0xffffffffu, x.x, partner);
    float py = __shfl_sync(0xffffffffu, x.y, partner);
    float pz = __shfl_sync(0xffffffffu, x.z, partner);
    float pw = __shfl_sync(0xffffffffu, x.w, partner);

    if (h0 < 80) {
        const float pos = (float)positions[m];
        const bool first = (h0 < 40);
        const float base_i = (float)(first ? h0 : h0 - 40);
        const float sgn = first ? -1.0f : 1.0f;
        float vals[4] = {x.x, x.y, x.z, x.w};
        float ps[4]   = {px, py, pz, pw};
        // timescale = 1e6^(i/40) = 2^(i * log2(1e6)/40)
        const float c2 = 0.49828921423310436f;
#pragma unroll
        for (int j = 0; j < 4; j++) {
            float fi = base_i + (float)j;
            float ts = exp2f(fi * c2);
            float ang = pos / ts;
            float s, c;
            sincosf(ang, &s, &c);                 // accurate version (large args)
            vals[j] = vals[j] * c + sgn * ps[j] * s;
        }
        x.x = vals[0]; x.y = vals[1]; x.z = vals[2]; x.w = vals[3];
    }
    *reinterpret_cast<float4*>(row + 4 * lane) = x;
}

// ---------------------------------------------------------------------------
// Causal GQA flash attention + fused sigmoid gating.
// One warp per query row (b, n, t); each lane owns 4 of H=128 dims.
// 8 warps/block are consecutive t with the same kv-head -> K/V rows hit L1.
// Output written gated into g_att[(b*T+t)*4096 + n*128 + h].
// ---------------------------------------------------------------------------
__global__ __launch_bounds__(256) void attn_kernel(
    const float* __restrict__ qg, const float* __restrict__ kbuf,
    const float* __restrict__ vbuf, float* __restrict__ gated)
{
    const int gw   = (blockIdx.x * blockDim.x + threadIdx.x) >> 5;
    const int lane = threadIdx.x & 31;

    const int t  = gw & 1023;        // T = 1024
    const int bn = gw >> 10;
    const int n  = bn & 31;          // N = 32
    const int b  = bn >> 5;
    const int kh = n >> 2;           // G = 4

    const float* qrow = qg + ((size_t)(b * 1024 + t)) * 8192 + n * 256;
    float4 q4 = *reinterpret_cast<const float4*>(qrow + 4 * lane);
    const float scale = 0.08838834764831845f;   // H^-0.5
    q4.x *= scale; q4.y *= scale; q4.z *= scale; q4.w *= scale;

    const float* kbase = kbuf + ((size_t)b * 1024) * 1024 + kh * 128 + 4 * lane;
    const float* vbase = vbuf + ((size_t)b * 1024) * 1024 + kh * 128 + 4 * lane;

    float m = -3.4e38f, l = 0.0f;
    float4 o = make_float4(0.f, 0.f, 0.f, 0.f);

    for (int s = 0; s <= t; s++) {
        float4 k4 = *reinterpret_cast<const float4*>(kbase + (size_t)s * 1024);
        float d = q4.x*k4.x + q4.y*k4.y + q4.z*k4.z + q4.w*k4.w;
#pragma unroll
        for (int off = 16; off; off >>= 1) d += __shfl_xor_sync(0xffffffffu, d, off);

        float mnew  = fmaxf(m, d);
        float alpha = __expf(m - mnew);
        float p     = __expf(d - mnew);
        float4 v4 = *reinterpret_cast<const float4*>(vbase + (size_t)s * 1024);
        l   = l * alpha + p;
        o.x = o.x * alpha + p * v4.x;
        o.y = o.y * alpha + p * v4.y;
        o.z = o.z * alpha + p * v4.z;
        o.w = o.w * alpha + p * v4.w;
        m = mnew;
    }

    const float inv = 1.0f / l;
    float4 g4 = *reinterpret_cast<const float4*>(qrow + 128 + 4 * lane);
    o.x = o.x * inv * (1.0f / (1.0f + __expf(-g4.x)));
    o.y = o.y * inv * (1.0f / (1.0f + __expf(-g4.y)));
    o.z = o.z * inv * (1.0f / (1.0f + __expf(-g4.z)));
    o.w = o.w * inv * (1.0f / (1.0f + __expf(-g4.w)));

    float* outp = gated + ((size_t)(b * 1024 + t)) * 4096 + n * 128 + 4 * lane;
    *reinterpret_cast<float4*>(outp) = o;
}

// ---------------------------------------------------------------------------
// Launcher: x, positions, wq, wk, wv, wo, q_norm_w, k_norm_w  ->  out (B,T,D)
// ---------------------------------------------------------------------------
extern "C" void kernel_launch(void* const* d_in, const int* in_sizes, int n_in,
                              void* d_out, int out_size)
{
    const float* x   = (const float*)d_in[0];
    const int*   pos = (const int*)  d_in[1];
    const float* wq  = (const float*)d_in[2];   // (4096, 8192)
    const float* wk  = (const float*)d_in[3];   // (4096, 1024)
    const float* wv  = (const float*)d_in[4];   // (4096, 1024)
    const float* wo  = (const float*)d_in[5];   // (4096, 4096)  [N*H, D]
    const float* qw  = (const float*)d_in[6];   // (128,)
    const float* kw  = (const float*)d_in[7];   // (128,)
    float* out = (float*)d_out;

    float *qg, *kb, *vb, *att;
    cudaGetSymbolAddress((void**)&qg,  g_qg);
    cudaGetSymbolAddress((void**)&kb,  g_k);
    cudaGetSymbolAddress((void**)&vb,  g_v);
    cudaGetSymbolAddress((void**)&att, g_att);

    const dim3 blk(256);

    // 1) Projections
    sgemm_kernel<<<dim3(8192 / BN, 4096 / BM), blk>>>(x, wq, qg, 4096, 8192, 4096);
    sgemm_kernel<<<dim3(1024 / BN, 4096 / BM), blk>>>(x, wk, kb, 4096, 1024, 4096);
    sgemm_kernel<<<dim3(1024 / BN, 4096 / BM), blk>>>(x, wv, vb, 4096, 1024, 4096);

    // 2) RMSNorm + RoPE (in place). q: 4096*32 rows, k: 4096*8 rows. 8 warps/block.
    norm_rope_kernel<<<(4096 * 32) / 8, 256>>>(qg, pos, qw, 32, 256, 8192);
    norm_rope_kernel<<<(4096 * 8) / 8, 256>>>(kb, pos, kw, 8, 128, 1024);

    // 3) Causal GQA attention + gating: 4*32*1024 = 131072 warps.
    attn_kernel<<<131072 / 8, blk>>>(qg, kb, vb, att);

    // 4) Output projection
    sgemm_kernel<<<dim3(4096 / BN, 4096 / BM), blk>>>(att, wo, out, 4096, 4096, 4096);
}

// round 3
// speedup vs baseline: 1.7917x; 1.7917x over previous
#include <cuda_runtime.h>
#include <cstdint>
#include <math.h>

// ============================================================================
// Shapes: B=4, T=1024, D=4096, N=32 heads, KH=8 kv heads, H=128, G=4
// M_TOK = 4096.  qg:(4096,8192)  k,v:(4096,1024)  att:(4096,4096)
// ============================================================================

__device__ float g_qg [4096UL * 8192];
__device__ float g_k  [4096UL * 1024];
__device__ float g_v  [4096UL * 1024];
__device__ float g_att[4096UL * 4096];

__device__ __forceinline__ uint32_t smem_u32(const void* p) {
    uint32_t a;
    asm("{ .reg .u64 t; cvta.to.shared.u64 t, %1; cvt.u32.u64 %0, t; }"
        : "=r"(a) : "l"(p));
    return a;
}
__device__ __forceinline__ float tf32r(float v) {
    uint32_t u;
    asm("cvt.rna.tf32.f32 %0, %1;" : "=r"(u) : "f"(v));
    return __uint_as_float(u);
}
__device__ __forceinline__ void cp16(uint32_t dst_smem, const void* src) {
    asm volatile("cp.async.cg.shared.global [%0], [%1], 16;"
                 :: "r"(dst_smem), "l"(src));
}
__device__ __forceinline__ void mma_tf32(float* d, const float* a, const float* b) {
    asm volatile(
        "mma.sync.aligned.m16n8k8.row.col.f32.tf32.tf32.f32 "
        "{%0,%1,%2,%3}, {%4,%5,%6,%7}, {%8,%9}, {%0,%1,%2,%3};"
        : "+f"(d[0]), "+f"(d[1]), "+f"(d[2]), "+f"(d[3])
        : "f"(a[0]), "f"(a[1]), "f"(a[2]), "f"(a[3]),
          "f"(b[0]), "f"(b[1]));
}

// ---------------------------------------------------------------------------
// tf32 mma.sync GEMM: C[M,N] = A[M,K] @ B[K,N], both row-major.
// CTA 128x128, BK=32, 8 warps (2x4), warp tile 64x32, 3-stage cp.async.
// As stride 36 floats, Bs stride 132 floats -> conflict-free fragment LDS.
// ---------------------------------------------------------------------------
#define BM 128
#define BN 128
#define BK 32
#define STAGES 3
#define AS_STRIDE 36
#define BS_STRIDE 132
#define A_FLOATS (BM * AS_STRIDE)          // 4608
#define B_FLOATS (BK * BS_STRIDE)          // 4224
#define STAGE_FLOATS (A_FLOATS + B_FLOATS) // 8832
#define GEMM_SMEM (STAGES * STAGE_FLOATS * 4)

__global__ __launch_bounds__(256, 1) void tf32_gemm(
    const float* __restrict__ A, const float* __restrict__ B,
    float* __restrict__ C, int M, int N, int K)
{
    extern __shared__ float smem[];
    const int tid  = threadIdx.x;
    const int wid  = tid >> 5;
    const int lane = tid & 31;
    const int g    = lane >> 2;      // group 0..7
    const int c    = lane & 3;       // 0..3

    const int m0 = blockIdx.y * BM;
    const int n0 = blockIdx.x * BN;
    const int m_warp = (wid & 1) * 64;   // 2 warps along M
    const int n_warp = (wid >> 1) * 32;  // 4 warps along N

    const int NKT = K / BK;

    float acc[4][4][4];
#pragma unroll
    for (int i = 0; i < 4; i++)
#pragma unroll
        for (int j = 0; j < 4; j++)
#pragma unroll
            for (int r = 0; r < 4; r++) acc[i][j][r] = 0.0f;

    // per-thread load coords
    const int ar  = tid >> 1;              // A row 0..127 (2 thr/row)
    const int ac4 = (tid & 1) * 4;         // A col 0 or 4 (x2 float4 per thread)
    const int br  = tid >> 3;              // B row 0..31
    const int bc4 = (tid & 7) * 4;         // B col base (x4 float4 per thread)

    auto load_tile = [&](int kt) {
        float* As = smem + (kt % STAGES) * STAGE_FLOATS;
        float* Bs = As + A_FLOATS;
        const int k0 = kt * BK;
        // A: 128x32 floats = 1024 float4 (256 thr x 4... here 2 rows-chunks x 2)
        const float* ap = &A[(size_t)(m0 + ar) * K + k0 + ac4];
        uint32_t ad = smem_u32(As + ar * AS_STRIDE + ac4);
        cp16(ad, ap);
        cp16(ad + 8 * 4, ap + 8);          // cols +8
        cp16(ad + 16 * 4, ap + 16);
        cp16(ad + 24 * 4, ap + 24);
        // B: 32x128 floats = 1024 float4
        const float* bp = &B[(size_t)(k0 + br) * N + n0 + bc4];
        uint32_t bd = smem_u32(Bs + br * BS_STRIDE + bc4);
        cp16(bd, bp);
        cp16(bd + 32 * 4, bp + 32);
        cp16(bd + 64 * 4, bp + 64);
        cp16(bd + 96 * 4, bp + 96);
        asm volatile("cp.async.commit_group;" ::: "memory");
    };

#pragma unroll
    for (int s = 0; s < STAGES - 1; s++) load_tile(s);

    for (int kt = 0; kt < NKT; kt++) {
        if (kt + STAGES - 1 < NKT) {
            asm volatile("cp.async.wait_group 1;" ::: "memory");
        } else {
            asm volatile("cp.async.wait_group 0;" ::: "memory");
        }
        __syncthreads();
        if (kt + STAGES - 1 < NKT) load_tile(kt + STAGES - 1);

        const float* As = smem + (kt % STAGES) * STAGE_FLOATS;
        const float* Bs = As + A_FLOATS;

#pragma unroll
        for (int ks = 0; ks < BK / 8; ks++) {
            const int k0 = ks * 8;
            float a[4][4], b[4][2];
#pragma unroll
            for (int mt = 0; mt < 4; mt++) {
                const float* ap = As + (m_warp + mt * 16 + g) * AS_STRIDE + k0 + c;
                a[mt][0] = tf32r(ap[0]);
                a[mt][1] = tf32r(ap[8 * AS_STRIDE]);
                a[mt][2] = tf32r(ap[4]);
                a[mt][3] = tf32r(ap[8 * AS_STRIDE + 4]);
            }
#pragma unroll
            for (int nt = 0; nt < 4; nt++) {
                const float* bp = Bs + (k0 + c) * BS_STRIDE + n_warp + nt * 8 + g;
                b[nt][0] = tf32r(bp[0]);
                b[nt][1] = tf32r(bp[4 * BS_STRIDE]);
            }
#pragma unroll
            for (int mt = 0; mt < 4; mt++)
#pragma unroll
                for (int nt = 0; nt < 4; nt++)
                    mma_tf32(acc[mt][nt], a[mt], b[nt]);
        }
        __syncthreads();
    }

    // epilogue
#pragma unroll
    for (int mt = 0; mt < 4; mt++) {
        const int row = m0 + m_warp + mt * 16 + g;
#pragma unroll
        for (int nt = 0; nt < 4; nt++) {
            const int col = n0 + n_warp + nt * 8 + c * 2;
            *reinterpret_cast<float2*>(&C[(size_t)row * N + col]) =
                make_float2(acc[mt][nt][0], acc[mt][nt][1]);
            *reinterpret_cast<float2*>(&C[(size_t)(row + 8) * N + col]) =
                make_float2(acc[mt][nt][2], acc[mt][nt][3]);
        }
    }
}

// ---------------------------------------------------------------------------
// Fused RMSNorm + RoPE, one warp per (token, head) row of 128 floats.
// ---------------------------------------------------------------------------
__global__ void norm_rope_kernel(
    float* __restrict__ buf, const int* __restrict__ positions,
    const float* __restrict__ w, int nheads, int head_stride, int row_stride)
{
    const int gw   = (blockIdx.x * blockDim.x + threadIdx.x) >> 5;
    const int lane = threadIdx.x & 31;
    const int h_idx = gw % nheads;
    const int m     = gw / nheads;

    float* row = buf + (size_t)m * row_stride + (size_t)h_idx * head_stride;
    float4 x = *reinterpret_cast<const float4*>(row + 4 * lane);

    float ss = x.x*x.x + x.y*x.y + x.z*x.z + x.w*x.w;
#pragma unroll
    for (int o = 16; o; o >>= 1) ss += __shfl_xor_sync(0xffffffffu, ss, o);
    float r = rsqrtf(ss * (1.0f / 128.0f) + 1e-6f);
    float4 wv = *reinterpret_cast<const float4*>(w + 4 * lane);
    x.x *= r * (1.0f + wv.x);
    x.y *= r * (1.0f + wv.y);
    x.z *= r * (1.0f + wv.z);
    x.w *= r * (1.0f + wv.w);

    const int h0 = lane * 4;
    const int partner = (lane < 10) ? lane + 10 : ((lane < 20) ? lane - 10 : lane);
    float px = __shfl_sync(0xffffffffu, x.x, partner);
    float py = __shfl_sync(0xffffffffu, x.y, partner);
    float pz = __shfl_sync(0xffffffffu, x.z, partner);
    float pw = __shfl_sync(0xffffffffu, x.w, partner);

    if (h0 < 80) {
        const float pos = (float)positions[m];
        const bool first = (h0 < 40);
        const float base_i = (float)(first ? h0 : h0 - 40);
        const float sgn = first ? -1.0f : 1.0f;
        float vals[4] = {x.x, x.y, x.z, x.w};
        float ps[4]   = {px, py, pz, pw};
        const float c2 = 0.49828921423310436f;    // log2(1e6)/40
#pragma unroll
        for (int j = 0; j < 4; j++) {
            float ts = exp2f((base_i + (float)j) * c2);
            float s, cc;
            sincosf(pos / ts, &s, &cc);
            vals[j] = vals[j] * cc + sgn * ps[j] * s;
        }
        x.x = vals[0]; x.y = vals[1]; x.z = vals[2]; x.w = vals[3];
    }
    *reinterpret_cast<float4*>(row + 4 * lane) = x;
}

// ---------------------------------------------------------------------------
// Causal GQA flash attention + sigmoid gating. One warp per (b, n, t).
// ---------------------------------------------------------------------------
__global__ __launch_bounds__(256) void attn_kernel(
    const float* __restrict__ qg, const float* __restrict__ kbuf,
    const float* __restrict__ vbuf, float* __restrict__ gated)
{
    const int gw   = (blockIdx.x * blockDim.x + threadIdx.x) >> 5;
    const int lane = threadIdx.x & 31;

    const int t  = gw & 1023;
    const int bn = gw >> 10;
    const int n  = bn & 31;
    const int b  = bn >> 5;
    const int kh = n >> 2;

    const float* qrow = qg + ((size_t)(b * 1024 + t)) * 8192 + n * 256;
    float4 q4 = *reinterpret_cast<const float4*>(qrow + 4 * lane);
    const float scale = 0.08838834764831845f;
    q4.x *= scale; q4.y *= scale; q4.z *= scale; q4.w *= scale;

    const float* kbase = kbuf + ((size_t)b * 1024) * 1024 + kh * 128 + 4 * lane;
    const float* vbase = vbuf + ((size_t)b * 1024) * 1024 + kh * 128 + 4 * lane;

    float m = -3.4e38f, l = 0.0f;
    float4 o = make_float4(0.f, 0.f, 0.f, 0.f);

    for (int s = 0; s <= t; s++) {
        float4 k4 = *reinterpret_cast<const float4*>(kbase + (size_t)s * 1024);
        float d = q4.x*k4.x + q4.y*k4.y + q4.z*k4.z + q4.w*k4.w;
#pragma unroll
        for (int off = 16; off; off >>= 1) d += __shfl_xor_sync(0xffffffffu, d, off);

        float mnew  = fmaxf(m, d);
        float alpha = __expf(m - mnew);
        float p     = __expf(d - mnew);
        float4 v4 = *reinterpret_cast<const float4*>(vbase + (size_t)s * 1024);
        l   = l * alpha + p;
        o.x = o.x * alpha + p * v4.x;
        o.y = o.y * alpha + p * v4.y;
        o.z = o.z * alpha + p * v4.z;
        o.w = o.w * alpha + p * v4.w;
        m = mnew;
    }

    const float inv = 1.0f / l;
    float4 g4 = *reinterpret_cast<const float4*>(qrow + 128 + 4 * lane);
    o.x = o.x * inv * (1.0f / (1.0f + __expf(-g4.x)));
    o.y = o.y * inv * (1.0f / (1.0f + __expf(-g4.y)));
    o.z = o.z * inv * (1.0f / (1.0f + __expf(-g4.z)));
    o.w = o.w * inv * (1.0f / (1.0f + __expf(-g4.w)));

    float* outp = gated + ((size_t)(b * 1024 + t)) * 4096 + n * 128 + 4 * lane;
    *reinterpret_cast<float4*>(outp) = o;
}

// ---------------------------------------------------------------------------
// Launcher
// ---------------------------------------------------------------------------
extern "C" void kernel_launch(void* const* d_in, const int* in_sizes, int n_in,
                              void* d_out, int out_size)
{
    const float* x   = (const float*)d_in[0];
    const int*   pos = (const int*)  d_in[1];
    const float* wq  = (const float*)d_in[2];   // (4096, 8192)
    const float* wk  = (const float*)d_in[3];   // (4096, 1024)
    const float* wv  = (const float*)d_in[4];   // (4096, 1024)
    const float* wo  = (const float*)d_in[5];   // (4096, 4096)
    const float* qw  = (const float*)d_in[6];
    const float* kw  = (const float*)d_in[7];
    float* out = (float*)d_out;

    float *qg, *kb, *vb, *att;
    cudaGetSymbolAddress((void**)&qg,  g_qg);
    cudaGetSymbolAddress((void**)&kb,  g_k);
    cudaGetSymbolAddress((void**)&vb,  g_v);
    cudaGetSymbolAddress((void**)&att, g_att);

    static bool attr_set = false;
    if (!attr_set) {
        cudaFuncSetAttribute(tf32_gemm, cudaFuncAttributeMaxDynamicSharedMemorySize,
                             GEMM_SMEM);
        attr_set = true;
    }

    // 1) Projections (tensor cores, tf32)
    tf32_gemm<<<dim3(8192 / BN, 4096 / BM), 256, GEMM_SMEM>>>(x, wq, qg, 4096, 8192, 4096);
    tf32_gemm<<<dim3(1024 / BN, 4096 / BM), 256, GEMM_SMEM>>>(x, wk, kb, 4096, 1024, 4096);
    tf32_gemm<<<dim3(1024 / BN, 4096 / BM), 256, GEMM_SMEM>>>(x, wv, vb, 4096, 1024, 4096);

    // 2) RMSNorm + RoPE
    norm_rope_kernel<<<(4096 * 32) / 8, 256>>>(qg, pos, qw, 32, 256, 8192);
    norm_rope_kernel<<<(4096 * 8) / 8, 256>>>(kb, pos, kw, 8, 128, 1024);

    // 3) Attention + gating
    attn_kernel<<<131072 / 8, 256>>>(qg, kb, vb, att);

    // 4) Output projection (tf32)
    tf32_gemm<<<dim3(4096 / BN, 4096 / BM), 256, GEMM_SMEM>>>(att, wo, out, 4096, 4096, 4096);
}

// round 4
// speedup vs baseline: 1.8907x; 1.0552x over previous
#include <cuda_runtime.h>
#include <cstdint>
#include <math.h>

// ============================================================================
// Shapes: B=4, T=1024, D=4096, N=32 heads, KH=8 kv heads, H=128, G=4
// M_TOK = 4096.  qg:(4096,8192)  k,v:(4096,1024)  att:(4096,4096)
// ============================================================================

__device__ float g_qg [4096UL * 8192];
__device__ float g_k  [4096UL * 1024];
__device__ float g_v  [4096UL * 1024];
__device__ float g_att[4096UL * 4096];

__device__ __forceinline__ uint32_t smem_u32(const void* p) {
    uint32_t a;
    asm("{ .reg .u64 t; cvta.to.shared.u64 t, %1; cvt.u32.u64 %0, t; }"
        : "=r"(a) : "l"(p));
    return a;
}
__device__ __forceinline__ float tf32r(float v) {
    uint32_t u;
    asm("cvt.rna.tf32.f32 %0, %1;" : "=r"(u) : "f"(v));
    return __uint_as_float(u);
}
__device__ __forceinline__ void cp16(uint32_t dst_smem, const void* src) {
    asm volatile("cp.async.cg.shared.global [%0], [%1], 16;"
                 :: "r"(dst_smem), "l"(src));
}
__device__ __forceinline__ void mma_tf32(float* d, const float* a, const float* b) {
    asm volatile(
        "mma.sync.aligned.m16n8k8.row.col.f32.tf32.tf32.f32 "
        "{%0,%1,%2,%3}, {%4,%5,%6,%7}, {%8,%9}, {%0,%1,%2,%3};"
        : "+f"(d[0]), "+f"(d[1]), "+f"(d[2]), "+f"(d[3])
        : "f"(a[0]), "f"(a[1]), "f"(a[2]), "f"(a[3]),
          "f"(b[0]), "f"(b[1]));
}

// ---------------------------------------------------------------------------
// tf32 mma.sync GEMM: C[M,N] = A[M,K] @ B[K,N], both row-major.
// CTA 128x256, BK=32, 8 warps (2x4), warp tile 64x64, 4-stage cp.async.
// As stride 36 (bank = 4g+c, conflict-free); Bs stride 264 (bank = 8c+g,
// conflict-free).
// ---------------------------------------------------------------------------
#define BM 128
#define BN 256
#define BK 32
#define STAGES 4
#define AS_STRIDE 36
#define BS_STRIDE 264
#define A_FLOATS (BM * AS_STRIDE)          // 4608
#define B_FLOATS (BK * BS_STRIDE)          // 8448
#define STAGE_FLOATS (A_FLOATS + B_FLOATS) // 13056
#define GEMM_SMEM (STAGES * STAGE_FLOATS * 4)   // 208896 B

__global__ __launch_bounds__(256, 1) void tf32_gemm(
    const float* __restrict__ A, const float* __restrict__ B,
    float* __restrict__ C, int M, int N, int K)
{
    extern __shared__ float smem[];
    const int tid  = threadIdx.x;
    const int wid  = tid >> 5;
    const int lane = tid & 31;
    const int g    = lane >> 2;      // group 0..7
    const int c    = lane & 3;       // 0..3

    const int m0 = blockIdx.y * BM;
    const int n0 = blockIdx.x * BN;
    const int m_warp = (wid & 1) * 64;   // 2 warps along M
    const int n_warp = (wid >> 1) * 64;  // 4 warps along N

    const int NKT = K / BK;

    float acc[4][8][4];
#pragma unroll
    for (int i = 0; i < 4; i++)
#pragma unroll
        for (int j = 0; j < 8; j++)
#pragma unroll
            for (int r = 0; r < 4; r++) acc[i][j][r] = 0.0f;

    // per-thread cp.async coords
    const int ar  = tid >> 1;              // A row 0..127 (2 thr/row)
    const int ac4 = (tid & 1) * 4;         // A col 0 or 4
    const int br  = tid >> 3;              // B row 0..31
    const int bc4 = (tid & 7) * 4;         // B col base

    auto load_tile = [&](int kt) {
        float* As = smem + (kt % STAGES) * STAGE_FLOATS;
        float* Bs = As + A_FLOATS;
        const int k0 = kt * BK;
        // A: 128x32 floats
        const float* ap = &A[(size_t)(m0 + ar) * K + k0 + ac4];
        uint32_t ad = smem_u32(As + ar * AS_STRIDE + ac4);
        cp16(ad, ap);
        cp16(ad + 8 * 4, ap + 8);
        cp16(ad + 16 * 4, ap + 16);
        cp16(ad + 24 * 4, ap + 24);
        // B: 32x256 floats
        const float* bp = &B[(size_t)(k0 + br) * N + n0 + bc4];
        uint32_t bd = smem_u32(Bs + br * BS_STRIDE + bc4);
#pragma unroll
        for (int j = 0; j < 8; j++)
            cp16(bd + j * 32 * 4, bp + j * 32);
        asm volatile("cp.async.commit_group;" ::: "memory");
    };

#pragma unroll
    for (int s = 0; s < STAGES - 1; s++) load_tile(s);

    for (int kt = 0; kt < NKT; kt++) {
        if (kt + STAGES - 1 < NKT) {
            asm volatile("cp.async.wait_group %0;" :: "n"(STAGES - 2) : "memory");
        } else {
            asm volatile("cp.async.wait_group 0;" ::: "memory");
        }
        __syncthreads();
        if (kt + STAGES - 1 < NKT) load_tile(kt + STAGES - 1);

        const float* As = smem + (kt % STAGES) * STAGE_FLOATS;
        const float* Bs = As + A_FLOATS;

#pragma unroll
        for (int ks = 0; ks < BK / 8; ks++) {
            const int k0 = ks * 8;
            float a[4][4], b[8][2];
#pragma unroll
            for (int mt = 0; mt < 4; mt++) {
                const float* ap = As + (m_warp + mt * 16 + g) * AS_STRIDE + k0 + c;
                a[mt][0] = tf32r(ap[0]);
                a[mt][1] = tf32r(ap[8 * AS_STRIDE]);
                a[mt][2] = tf32r(ap[4]);
                a[mt][3] = tf32r(ap[8 * AS_STRIDE + 4]);
            }
#pragma unroll
            for (int nt = 0; nt < 8; nt++) {
                const float* bp = Bs + (k0 + c) * BS_STRIDE + n_warp + nt * 8 + g;
                b[nt][0] = tf32r(bp[0]);
                b[nt][1] = tf32r(bp[4 * BS_STRIDE]);
            }
#pragma unroll
            for (int mt = 0; mt < 4; mt++)
#pragma unroll
                for (int nt = 0; nt < 8; nt++)
                    mma_tf32(acc[mt][nt], a[mt], b[nt]);
        }
        __syncthreads();
    }

    // epilogue
#pragma unroll
    for (int mt = 0; mt < 4; mt++) {
        const int row = m0 + m_warp + mt * 16 + g;
#pragma unroll
        for (int nt = 0; nt < 8; nt++) {
            const int col = n0 + n_warp + nt * 8 + c * 2;
            *reinterpret_cast<float2*>(&C[(size_t)row * N + col]) =
                make_float2(acc[mt][nt][0], acc[mt][nt][1]);
            *reinterpret_cast<float2*>(&C[(size_t)(row + 8) * N + col]) =
                make_float2(acc[mt][nt][2], acc[mt][nt][3]);
        }
    }
}

// ---------------------------------------------------------------------------
// Fused RMSNorm + RoPE, one warp per (token, head) row of 128 floats.
// ---------------------------------------------------------------------------
__global__ void norm_rope_kernel(
    float* __restrict__ buf, const int* __restrict__ positions,
    const float* __restrict__ w, int nheads, int head_stride, int row_stride)
{
    const int gw   = (blockIdx.x * blockDim.x + threadIdx.x) >> 5;
    const int lane = threadIdx.x & 31;
    const int h_idx = gw % nheads;
    const int m     = gw / nheads;

    float* row = buf + (size_t)m * row_stride + (size_t)h_idx * head_stride;
    float4 x = *reinterpret_cast<const float4*>(row + 4 * lane);

    float ss = x.x*x.x + x.y*x.y + x.z*x.z + x.w*x.w;
#pragma unroll
    for (int o = 16; o; o >>= 1) ss += __shfl_xor_sync(0xffffffffu, ss, o);
    float r = rsqrtf(ss * (1.0f / 128.0f) + 1e-6f);
    float4 wv = *reinterpret_cast<const float4*>(w + 4 * lane);
    x.x *= r * (1.0f + wv.x);
    x.y *= r * (1.0f + wv.y);
    x.z *= r * (1.0f + wv.z);
    x.w *= r * (1.0f + wv.w);

    const int h0 = lane * 4;
    const int partner = (lane < 10) ? lane + 10 : ((lane < 20) ? lane - 10 : lane);
    float px = __shfl_sync(0xffffffffu, x.x, partner);
    float py = __shfl_sync(0xffffffffu, x.y, partner);
    float pz = __shfl_sync(0xffffffffu, x.z, partner);
    float pw = __shfl_sync(0xffffffffu, x.w, partner);

    if (h0 < 80) {
        const float pos = (float)positions[m];
        const bool first = (h0 < 40);
        const float base_i = (float)(first ? h0 : h0 - 40);
        const float sgn = first ? -1.0f : 1.0f;
        float vals[4] = {x.x, x.y, x.z, x.w};
        float ps[4]   = {px, py, pz, pw};
        const float c2 = 0.49828921423310436f;    // log2(1e6)/40
#pragma unroll
        for (int j = 0; j < 4; j++) {
            float ts = exp2f((base_i + (float)j) * c2);
            float s, cc;
            sincosf(pos / ts, &s, &cc);
            vals[j] = vals[j] * cc + sgn * ps[j] * s;
        }
        x.x = vals[0]; x.y = vals[1]; x.z = vals[2]; x.w = vals[3];
    }
    *reinterpret_cast<float4*>(row + 4 * lane) = x;
}

// ---------------------------------------------------------------------------
// Causal GQA flash attention + sigmoid gating. One warp per (b, n, t).
// ---------------------------------------------------------------------------
__global__ __launch_bounds__(256) void attn_kernel(
    const float* __restrict__ qg, const float* __restrict__ kbuf,
    const float* __restrict__ vbuf, float* __restrict__ gated)
{
    const int gw   = (blockIdx.x * blockDim.x + threadIdx.x) >> 5;
    const int lane = threadIdx.x & 31;

    const int t  = gw & 1023;
    const int bn = gw >> 10;
    const int n  = bn & 31;
    const int b  = bn >> 5;
    const int kh = n >> 2;

    const float* qrow = qg + ((size_t)(b * 1024 + t)) * 8192 + n * 256;
    float4 q4 = *reinterpret_cast<const float4*>(qrow + 4 * lane);
    const float scale = 0.08838834764831845f;
    q4.x *= scale; q4.y *= scale; q4.z *= scale; q4.w *= scale;

    const float* kbase = kbuf + ((size_t)b * 1024) * 1024 + kh * 128 + 4 * lane;
    const float* vbase = vbuf + ((size_t)b * 1024) * 1024 + kh * 128 + 4 * lane;

    float m = -3.4e38f, l = 0.0f;
    float4 o = make_float4(0.f, 0.f, 0.f, 0.f);

    for (int s = 0; s <= t; s++) {
        float4 k4 = *reinterpret_cast<const float4*>(kbase + (size_t)s * 1024);
        float d = q4.x*k4.x + q4.y*k4.y + q4.z*k4.z + q4.w*k4.w;
#pragma unroll
        for (int off = 16; off; off >>= 1) d += __shfl_xor_sync(0xffffffffu, d, off);

        float mnew  = fmaxf(m, d);
        float alpha = __expf(m - mnew);
        float p     = __expf(d - mnew);
        float4 v4 = *reinterpret_cast<const float4*>(vbase + (size_t)s * 1024);
        l   = l * alpha + p;
        o.x = o.x * alpha + p * v4.x;
        o.y = o.y * alpha + p * v4.y;
        o.z = o.z * alpha + p * v4.z;
        o.w = o.w * alpha + p * v4.w;
        m = mnew;
    }

    const float inv = 1.0f / l;
    float4 g4 = *reinterpret_cast<const float4*>(qrow + 128 + 4 * lane);
    o.x = o.x * inv * (1.0f / (1.0f + __expf(-g4.x)));
    o.y = o.y * inv * (1.0f / (1.0f + __expf(-g4.y)));
    o.z = o.z * inv * (1.0f / (1.0f + __expf(-g4.z)));
    o.w = o.w * inv * (1.0f / (1.0f + __expf(-g4.w)));

    float* outp = gated + ((size_t)(b * 1024 + t)) * 4096 + n * 128 + 4 * lane;
    *reinterpret_cast<float4*>(outp) = o;
}

// ---------------------------------------------------------------------------
// Launcher
// ---------------------------------------------------------------------------
extern "C" void kernel_launch(void* const* d_in, const int* in_sizes, int n_in,
                              void* d_out, int out_size)
{
    const float* x   = (const float*)d_in[0];
    const int*   pos = (const int*)  d_in[1];
    const float* wq  = (const float*)d_in[2];   // (4096, 8192)
    const float* wk  = (const float*)d_in[3];   // (4096, 1024)
    const float* wv  = (const float*)d_in[4];   // (4096, 1024)
    const float* wo  = (const float*)d_in[5];   // (4096, 4096)
    const float* qw  = (const float*)d_in[6];
    const float* kw  = (const float*)d_in[7];
    float* out = (float*)d_out;

    float *qg, *kb, *vb, *att;
    cudaGetSymbolAddress((void**)&qg,  g_qg);
    cudaGetSymbolAddress((void**)&kb,  g_k);
    cudaGetSymbolAddress((void**)&vb,  g_v);
    cudaGetSymbolAddress((void**)&att, g_att);

    static bool attr_set = false;
    if (!attr_set) {
        cudaFuncSetAttribute(tf32_gemm, cudaFuncAttributeMaxDynamicSharedMemorySize,
                             GEMM_SMEM);
        attr_set = true;
    }

    // 1) Projections (tensor cores, tf32)
    tf32_gemm<<<dim3(8192 / BN, 4096 / BM), 256, GEMM_SMEM>>>(x, wq, qg, 4096, 8192, 4096);
    tf32_gemm<<<dim3(1024 / BN, 4096 / BM), 256, GEMM_SMEM>>>(x, wk, kb, 4096, 1024, 4096);
    tf32_gemm<<<dim3(1024 / BN, 4096 / BM), 256, GEMM_SMEM>>>(x, wv, vb, 4096, 1024, 4096);

    // 2) RMSNorm + RoPE
    norm_rope_kernel<<<(4096 * 32) / 8, 256>>>(qg, pos, qw, 32, 256, 8192);
    norm_rope_kernel<<<(4096 * 8) / 8, 256>>>(kb, pos, kw, 8, 128, 1024);

    // 3) Attention + gating
    attn_kernel<<<131072 / 8, 256>>>(qg, kb, vb, att);

    // 4) Output projection (tf32)
    tf32_gemm<<<dim3(4096 / BN, 4096 / BM), 256, GEMM_SMEM>>>(att, wo, out, 4096, 4096, 4096);
}

// round 5
// speedup vs baseline: 2.3255x; 1.2300x over previous
#include <cuda_runtime.h>
#include <cuda_fp16.h>
#include <cstdint>
#include <math.h>

// ============================================================================
// Shapes: B=4, T=1024, D=4096, N=32 heads, KH=8 kv heads, H=128, G=4
// M_TOK = 4096.  qg:(4096,8192)  k,v:(4096,1024)  att:(4096,4096)
// ============================================================================

__device__ float  g_qg [4096UL * 8192];
__device__ float  g_k  [4096UL * 1024];
__device__ float  g_v  [4096UL * 1024];
__device__ __half g_xh  [4096UL * 4096];
__device__ __half g_wqh [4096UL * 8192];
__device__ __half g_wkh [4096UL * 1024];
__device__ __half g_wvh [4096UL * 1024];
__device__ __half g_woh [4096UL * 4096];
__device__ __half g_atth[4096UL * 4096];

__device__ __forceinline__ uint32_t smem_u32(const void* p) {
    uint32_t a;
    asm("{ .reg .u64 t; cvta.to.shared.u64 t, %1; cvt.u32.u64 %0, t; }"
        : "=r"(a) : "l"(p));
    return a;
}
__device__ __forceinline__ void cp16(uint32_t dst_smem, const void* src) {
    asm volatile("cp.async.cg.shared.global [%0], [%1], 16;"
                 :: "r"(dst_smem), "l"(src));
}
__device__ __forceinline__ void ldsm4(uint32_t* r, uint32_t addr) {
    asm volatile("ldmatrix.sync.aligned.m8n8.x4.shared.b16 {%0,%1,%2,%3}, [%4];"
                 : "=r"(r[0]), "=r"(r[1]), "=r"(r[2]), "=r"(r[3]) : "r"(addr));
}
__device__ __forceinline__ void ldsm4t(uint32_t* r, uint32_t addr) {
    asm volatile("ldmatrix.sync.aligned.m8n8.x4.trans.shared.b16 {%0,%1,%2,%3}, [%4];"
                 : "=r"(r[0]), "=r"(r[1]), "=r"(r[2]), "=r"(r[3]) : "r"(addr));
}
__device__ __forceinline__ void mma_f16(float* d, const uint32_t* a,
                                        uint32_t b0, uint32_t b1) {
    asm volatile(
        "mma.sync.aligned.m16n8k16.row.col.f32.f16.f16.f32 "
        "{%0,%1,%2,%3}, {%4,%5,%6,%7}, {%8,%9}, {%0,%1,%2,%3};"
        : "+f"(d[0]), "+f"(d[1]), "+f"(d[2]), "+f"(d[3])
        : "r"(a[0]), "r"(a[1]), "r"(a[2]), "r"(a[3]), "r"(b0), "r"(b1));
}

// ---------------------------------------------------------------------------
// fp16 mma.sync GEMM: C[M,N](fp32) = A[M,K](half) @ B[K,N](half), row-major.
// CTA 128x256, BK=64, 8 warps (2x4), warp tile 64x64, 3-stage cp.async,
// XOR-swizzled smem (16B chunk ^= row&7) -> conflict-free ldmatrix.
// ---------------------------------------------------------------------------
#define BM 128
#define BN 256
#define BK 64
#define STAGES 3
#define A_BYTES (128 * 128)                 // 128 rows x 64 halves
#define B_BYTES (64 * 512)                  // 64 rows x 256 halves
#define STAGE_BYTES (A_BYTES + B_BYTES)     // 49152
#define GEMM_SMEM (STAGES * STAGE_BYTES)    // 147456

__global__ __launch_bounds__(256, 1) void h16_gemm(
    const __half* __restrict__ A, const __half* __restrict__ B,
    float* __restrict__ C, int M, int N, int K)
{
    extern __shared__ char smem[];
    const uint32_t sbase = smem_u32(smem);
    const int tid  = threadIdx.x;
    const int wid  = tid >> 5;
    const int lane = tid & 31;
    const int g    = lane >> 2;
    const int c    = lane & 3;

    const int m0 = blockIdx.y * BM;
    const int n0 = blockIdx.x * BN;
    const int m_warp = (wid & 1) * 64;
    const int n_warp = (wid >> 1) * 64;
    const int NKT = K / BK;

    float acc[4][8][4];
#pragma unroll
    for (int i = 0; i < 4; i++)
#pragma unroll
        for (int j = 0; j < 8; j++)
#pragma unroll
            for (int r = 0; r < 4; r++) acc[i][j][r] = 0.0f;

    // cp.async coords
    const int ar  = tid >> 1;               // A row 0..127, 2 thr/row
    const int ac  = tid & 1;                //   4 chunks each
    const int brr = tid >> 2;               // B row 0..63, 4 thr/row
    const int bcg = tid & 3;                //   8 chunks each

    // ldmatrix lane-local offsets
    const int lrow = (lane & 7) + ((lane >> 3) & 1) * 8;  // row within 16
    const int lkc  = lane >> 4;                           // chunk offset 0/1
    const int lxor = lane & 7;

    auto load_tile = [&](int kt) {
        const uint32_t sa = sbase + (kt % STAGES) * STAGE_BYTES;
        const uint32_t sb = sa + A_BYTES;
        const int k0 = kt * BK;
        const __half* ap = A + (size_t)(m0 + ar) * K + k0 + ac * 32;
#pragma unroll
        for (int j = 0; j < 4; j++) {
            int ch = ac * 4 + j;
            cp16(sa + ar * 128 + ((ch ^ (ar & 7)) * 16), ap + j * 8);
        }
        const __half* bp = B + (size_t)(k0 + brr) * N + n0 + bcg * 64;
#pragma unroll
        for (int j = 0; j < 8; j++) {
            int ch = bcg * 8 + j;
            cp16(sb + brr * 512 + ((ch ^ (brr & 7)) * 16), bp + j * 8);
        }
        asm volatile("cp.async.commit_group;" ::: "memory");
    };

#pragma unroll
    for (int s = 0; s < STAGES - 1; s++) load_tile(s);

    for (int kt = 0; kt < NKT; kt++) {
        if (kt + STAGES - 1 < NKT) {
            asm volatile("cp.async.wait_group %0;" :: "n"(STAGES - 2) : "memory");
        } else {
            asm volatile("cp.async.wait_group 0;" ::: "memory");
        }
        __syncthreads();
        if (kt + STAGES - 1 < NKT) load_tile(kt + STAGES - 1);

        const uint32_t sa = sbase + (kt % STAGES) * STAGE_BYTES;
        const uint32_t sb = sa + A_BYTES;

#pragma unroll
        for (int ks = 0; ks < BK / 16; ks++) {
            uint32_t a[4][4], b[4][4];
#pragma unroll
            for (int mt = 0; mt < 4; mt++) {
                int row = m_warp + mt * 16 + lrow;
                ldsm4(a[mt], sa + row * 128 + (((ks * 2 + lkc) ^ lxor) * 16));
            }
#pragma unroll
            for (int p = 0; p < 4; p++) {
                int krow = ks * 16 + lrow;
                int nc = (n_warp >> 3) + p * 2 + lkc;
                ldsm4t(b[p], sb + krow * 512 + ((nc ^ lxor) * 16));
            }
#pragma unroll
            for (int mt = 0; mt < 4; mt++)
#pragma unroll
                for (int p = 0; p < 4; p++) {
                    mma_f16(acc[mt][2 * p],     a[mt], b[p][0], b[p][1]);
                    mma_f16(acc[mt][2 * p + 1], a[mt], b[p][2], b[p][3]);
                }
        }
        __syncthreads();
    }

    // epilogue
#pragma unroll
    for (int mt = 0; mt < 4; mt++) {
        const int row = m0 + m_warp + mt * 16 + g;
#pragma unroll
        for (int nt = 0; nt < 8; nt++) {
            const int col = n0 + n_warp + nt * 8 + c * 2;
            *reinterpret_cast<float2*>(&C[(size_t)row * N + col]) =
                make_float2(acc[mt][nt][0], acc[mt][nt][1]);
            *reinterpret_cast<float2*>(&C[(size_t)(row + 8) * N + col]) =
                make_float2(acc[mt][nt][2], acc[mt][nt][3]);
        }
    }
}

// ---------------------------------------------------------------------------
// float -> half conversion (element counts are multiples of 1024)
// ---------------------------------------------------------------------------
__global__ void f2h_kernel(const float* __restrict__ in, __half* __restrict__ out)
{
    const int i = (blockIdx.x * blockDim.x + threadIdx.x) * 4;
    float4 v = *reinterpret_cast<const float4*>(in + i);
    __half2 h0 = __floats2half2_rn(v.x, v.y);
    __half2 h1 = __floats2half2_rn(v.z, v.w);
    *reinterpret_cast<__half2*>(out + i)     = h0;
    *reinterpret_cast<__half2*>(out + i + 2) = h1;
}

// ---------------------------------------------------------------------------
// Fused RMSNorm + RoPE, one warp per (token, head) row of 128 floats.
// ---------------------------------------------------------------------------
__global__ void norm_rope_kernel(
    float* __restrict__ buf, const int* __restrict__ positions,
    const float* __restrict__ w, int nheads, int head_stride, int row_stride)
{
    const int gw   = (blockIdx.x * blockDim.x + threadIdx.x) >> 5;
    const int lane = threadIdx.x & 31;
    const int h_idx = gw % nheads;
    const int m     = gw / nheads;

    float* row = buf + (size_t)m * row_stride + (size_t)h_idx * head_stride;
    float4 x = *reinterpret_cast<const float4*>(row + 4 * lane);

    float ss = x.x*x.x + x.y*x.y + x.z*x.z + x.w*x.w;
#pragma unroll
    for (int o = 16; o; o >>= 1) ss += __shfl_xor_sync(0xffffffffu, ss, o);
    float r = rsqrtf(ss * (1.0f / 128.0f) + 1e-6f);
    float4 wv = *reinterpret_cast<const float4*>(w + 4 * lane);
    x.x *= r * (1.0f + wv.x);
    x.y *= r * (1.0f + wv.y);
    x.z *= r * (1.0f + wv.z);
    x.w *= r * (1.0f + wv.w);

    const int h0 = lane * 4;
    const int partner = (lane < 10) ? lane + 10 : ((lane < 20) ? lane - 10 : lane);
    float px = __shfl_sync(0xffffffffu, x.x, partner);
    float py = __shfl_sync(0xffffffffu, x.y, partner);
    float pz = __shfl_sync(0xffffffffu, x.z, partner);
    float pw = __shfl_sync(0xffffffffu, x.w, partner);

    if (h0 < 80) {
        const float pos = (float)positions[m];
        const bool first = (h0 < 40);
        const float base_i = (float)(first ? h0 : h0 - 40);
        const float sgn = first ? -1.0f : 1.0f;
        float vals[4] = {x.x, x.y, x.z, x.w};
        float ps[4]   = {px, py, pz, pw};
        const float c2 = 0.49828921423310436f;    // log2(1e6)/40
#pragma unroll
        for (int j = 0; j < 4; j++) {
            float ts = exp2f((base_i + (float)j) * c2);
            float s, cc;
            sincosf(pos / ts, &s, &cc);
            vals[j] = vals[j] * cc + sgn * ps[j] * s;
        }
        x.x = vals[0]; x.y = vals[1]; x.z = vals[2]; x.w = vals[3];
    }
    *reinterpret_cast<float4*>(row + 4 * lane) = x;
}

// ---------------------------------------------------------------------------
// Causal GQA flash attention + sigmoid gating. One warp per (b, n, t).
// Output written as half (A operand of the fp16 out-projection).
// ---------------------------------------------------------------------------
__global__ __launch_bounds__(256) void attn_kernel(
    const float* __restrict__ qg, const float* __restrict__ kbuf,
    const float* __restrict__ vbuf, __half* __restrict__ gated)
{
    const int gw   = (blockIdx.x * blockDim.x + threadIdx.x) >> 5;
    const int lane = threadIdx.x & 31;

    const int t  = gw & 1023;
    const int bn = gw >> 10;
    const int n  = bn & 31;
    const int b  = bn >> 5;
    const int kh = n >> 2;

    const float* qrow = qg + ((size_t)(b * 1024 + t)) * 8192 + n * 256;
    float4 q4 = *reinterpret_cast<const float4*>(qrow + 4 * lane);
    const float scale = 0.08838834764831845f;
    q4.x *= scale; q4.y *= scale; q4.z *= scale; q4.w *= scale;

    const float* kbase = kbuf + ((size_t)b * 1024) * 1024 + kh * 128 + 4 * lane;
    const float* vbase = vbuf + ((size_t)b * 1024) * 1024 + kh * 128 + 4 * lane;

    float m = -3.4e38f, l = 0.0f;
    float4 o = make_float4(0.f, 0.f, 0.f, 0.f);

    for (int s = 0; s <= t; s++) {
        float4 k4 = *reinterpret_cast<const float4*>(kbase + (size_t)s * 1024);
        float d = q4.x*k4.x + q4.y*k4.y + q4.z*k4.z + q4.w*k4.w;
#pragma unroll
        for (int off = 16; off; off >>= 1) d += __shfl_xor_sync(0xffffffffu, d, off);

        float mnew  = fmaxf(m, d);
        float alpha = __expf(m - mnew);
        float p     = __expf(d - mnew);
        float4 v4 = *reinterpret_cast<const float4*>(vbase + (size_t)s * 1024);
        l   = l * alpha + p;
        o.x = o.x * alpha + p * v4.x;
        o.y = o.y * alpha + p * v4.y;
        o.z = o.z * alpha + p * v4.z;
        o.w = o.w * alpha + p * v4.w;
        m = mnew;
    }

    const float inv = 1.0f / l;
    float4 g4 = *reinterpret_cast<const float4*>(qrow + 128 + 4 * lane);
    o.x = o.x * inv * (1.0f / (1.0f + __expf(-g4.x)));
    o.y = o.y * inv * (1.0f / (1.0f + __expf(-g4.y)));
    o.z = o.z * inv * (1.0f / (1.0f + __expf(-g4.z)));
    o.w = o.w * inv * (1.0f / (1.0f + __expf(-g4.w)));

    __half2* outp = reinterpret_cast<__half2*>(
        gated + ((size_t)(b * 1024 + t)) * 4096 + n * 128 + 4 * lane);
    outp[0] = __floats2half2_rn(o.x, o.y);
    outp[1] = __floats2half2_rn(o.z, o.w);
}

// ---------------------------------------------------------------------------
// Launcher
// ---------------------------------------------------------------------------
extern "C" void kernel_launch(void* const* d_in, const int* in_sizes, int n_in,
                              void* d_out, int out_size)
{
    const float* x   = (const float*)d_in[0];
    const int*   pos = (const int*)  d_in[1];
    const float* wq  = (const float*)d_in[2];   // (4096, 8192)
    const float* wk  = (const float*)d_in[3];   // (4096, 1024)
    const float* wv  = (const float*)d_in[4];   // (4096, 1024)
    const float* wo  = (const float*)d_in[5];   // (4096, 4096)
    const float* qw  = (const float*)d_in[6];
    const float* kw  = (const float*)d_in[7];
    float* out = (float*)d_out;

    float  *qg, *kb, *vb;
    __half *xh, *wqh, *wkh, *wvh, *woh, *atth;
    cudaGetSymbolAddress((void**)&qg,   g_qg);
    cudaGetSymbolAddress((void**)&kb,   g_k);
    cudaGetSymbolAddress((void**)&vb,   g_v);
    cudaGetSymbolAddress((void**)&xh,   g_xh);
    cudaGetSymbolAddress((void**)&wqh,  g_wqh);
    cudaGetSymbolAddress((void**)&wkh,  g_wkh);
    cudaGetSymbolAddress((void**)&wvh,  g_wvh);
    cudaGetSymbolAddress((void**)&woh,  g_woh);
    cudaGetSymbolAddress((void**)&atth, g_atth);

    static bool attr_set = false;
    if (!attr_set) {
        cudaFuncSetAttribute(h16_gemm, cudaFuncAttributeMaxDynamicSharedMemorySize,
                             GEMM_SMEM);
        attr_set = true;
    }

    // 0) fp32 -> fp16 conversions (x + all weights)
    f2h_kernel<<<(4096UL * 4096) / 1024, 256>>>(x,  xh);
    f2h_kernel<<<(4096UL * 8192) / 1024, 256>>>(wq, wqh);
    f2h_kernel<<<(4096UL * 1024) / 1024, 256>>>(wk, wkh);
    f2h_kernel<<<(4096UL * 1024) / 1024, 256>>>(wv, wvh);
    f2h_kernel<<<(4096UL * 4096) / 1024, 256>>>(wo, woh);

    // 1) Projections (fp16 tensor cores, fp32 accumulate)
    h16_gemm<<<dim3(8192 / BN, 4096 / BM), 256, GEMM_SMEM>>>(xh, wqh, qg, 4096, 8192, 4096);
    h16_gemm<<<dim3(1024 / BN, 4096 / BM), 256, GEMM_SMEM>>>(xh, wkh, kb, 4096, 1024, 4096);
    h16_gemm<<<dim3(1024 / BN, 4096 / BM), 256, GEMM_SMEM>>>(xh, wvh, vb, 4096, 1024, 4096);

    // 2) RMSNorm + RoPE (fp32)
    norm_rope_kernel<<<(4096 * 32) / 8, 256>>>(qg, pos, qw, 32, 256, 8192);
    norm_rope_kernel<<<(4096 * 8) / 8, 256>>>(kb, pos, kw, 8, 128, 1024);

    // 3) Attention + gating (fp32 compute, half output)
    attn_kernel<<<131072 / 8, 256>>>(qg, kb, vb, atth);

    // 4) Output projection (fp16 tensor cores)
    h16_gemm<<<dim3(4096 / BN, 4096 / BM), 256, GEMM_SMEM>>>(atth, woh, out, 4096, 4096, 4096);
}